// round 15
// baseline (speedup 1.0000x reference)
#include <cuda_runtime.h>
#include <cstdint>
#include <math.h>

#define DEG 3
#define NM 32          // MU_MAX = MV_MAX
#define NU 64          // OUT_U = OUT_V
#define BATCH 1024
#define EPSI 1e-5f

// per-block partials: x = surf-sq-err sum, y = ctrl-sq-err sum, z = mask sum
__device__ float4 g_part[BATCH];
__device__ unsigned g_count = 0;   // last-block counter; reset each launch

// clamped open-uniform knot, n_valid = m ctrl pts (matches reference padding)
__device__ __forceinline__ float kvf(int k, int m) {
    if (k <= DEG) return 0.0f;
    if (k >= m)   return 1.0f;
    return (float)k / (float)(m + DEG);
}

// ---------------- smem layout (floats) ----------------
//  sC4   float4[1024]     : 0      ctrl_pred padded xyz_ (16 KB)
//  wU4   float4[64]       : 4096
//  wV4   float4[64]       : 4352
//  baseU int[64]          : 4608
//  baseV int[64]          : 4672
//  sT4   float4[8][2][32] : 4736   per-warp double-buffered padded T tile (8 KB)
//  total 6784 floats = 27136 B
#define SMEM_FLOATS 6784

__global__ __launch_bounds__(256, 4)
void surf_loss_kernel(const float* __restrict__ ctrl_pred,
                      const float* __restrict__ ctrl_gt,
                      const float* __restrict__ mask,
                      const float* __restrict__ xyz,
                      float* __restrict__ out) {
    extern __shared__ float sm[];
    float4* sC4   = (float4*)sm;
    float4* wU4   = (float4*)(sm + 4096);
    float4* wV4   = (float4*)(sm + 4352);
    int*    baseU = (int*)(sm + 4608);
    int*    baseV = (int*)(sm + 4672);
    float4* sT4   = (float4*)(sm + 4736);

    __shared__ float rS[8], rC[8];
    __shared__ int s_mu, s_last;

    const int b    = blockIdx.x;
    const int tid  = threadIdx.x;
    const int lane = tid & 31;
    const int warp = tid >> 5;

    // ================== PROLOGUE: issue long-latency loads first ==================
    const float* mk = mask + (size_t)b * (NM * NM);
    float mrow = mk[lane];                                   // row 0 -> mv (all warps: 1 line)
    float mcol = (warp < 2) ? mk[lane * NM] : 0.0f;          // col 0 -> mu (warps 0-1 only)

    const float4* cp4 = (const float4*)(ctrl_pred + (size_t)b * (NM * NM * 3));
    const float4* cg4 = (const float4*)(ctrl_gt   + (size_t)b * (NM * NM * 3));
    const int kc = 3 * tid;
    float4 p0 = __ldcs(&cp4[kc]), p1 = __ldcs(&cp4[kc + 1]), p2 = __ldcs(&cp4[kc + 2]);
    float4 g0 = __ldcs(&cg4[kc]), g1 = __ldcs(&cg4[kc + 1]), g2 = __ldcs(&cg4[kc + 2]);

    const float* xw = xyz + (size_t)b * (NU * NU * 3) + (warp * 8) * 192 + 6 * lane;
    float2 A0 = __ldcs((const float2*)(xw));
    float2 A1 = __ldcs((const float2*)(xw + 2));
    float2 A2 = __ldcs((const float2*)(xw + 4));

    // ---- ragged sizes ----
    unsigned bmv = __ballot_sync(0xffffffffu, mrow > 0.0f);
    const int mv = max(__popc(bmv), DEG + 1);
    int mu = DEG + 1;
    if (warp < 2) {
        unsigned bmu = __ballot_sync(0xffffffffu, mcol > 0.0f);
        mu = max(__popc(bmu), DEG + 1);
    }
    if (tid == 0) s_mu = mu;

    // ---- local de Boor: warps 0-1 use mu (they have it), warps 2-3 use mv ----
    if (tid < 128) {
        int dim = tid >> 6, g = tid & 63;
        int m = dim ? mv : mu;
        float x = EPSI + ((1.0f - 2.0f * EPSI) / 63.0f) * (float)g;
        int s = (int)(x * (float)(m + DEG));
        s = max(s, DEG); s = min(s, m - 1);
        while (s < m - 1 && x >= kvf(s + 1, m)) s++;
        while (s > DEG && x < kvf(s, m)) s--;
        float N[4]; N[0] = 1.0f; N[1] = N[2] = N[3] = 0.0f;
        float left[4], right[4];
#pragma unroll
        for (int d = 1; d <= DEG; d++) {
            left[d]  = x - kvf(s + 1 - d, m);
            right[d] = kvf(s + d, m) - x;
            float saved = 0.0f;
#pragma unroll
            for (int r = 0; r < d; r++) {
                float tmp = N[r] / (right[r + 1] + left[d - r]);
                N[r] = saved + right[r + 1] * tmp;
                saved = left[d - r] * tmp;
            }
            N[d] = saved;
        }
        float inv = 1.0f / (N[0] + N[1] + N[2] + N[3]);  // partition denom
        float4 w = make_float4(N[0] * inv, N[1] * inv, N[2] * inv, N[3] * inv);
        if (dim == 0) { wU4[g] = w; baseU[g] = s - DEG; }
        else          { wV4[g] = w; baseV[g] = s - DEG; }
    }

    // ---- repack ctrl into padded float4 smem + squared diffs (guard after barrier) ----
    const int c0 = 4 * tid;
    float ss0, ss1, ss2, ss3;
    {
        sC4[c0    ] = make_float4(p0.x, p0.y, p0.z, 0.0f);
        sC4[c0 + 1] = make_float4(p0.w, p1.x, p1.y, 0.0f);
        sC4[c0 + 2] = make_float4(p1.z, p1.w, p2.x, 0.0f);
        sC4[c0 + 3] = make_float4(p2.y, p2.z, p2.w, 0.0f);
        float d;
        d = p0.x - g0.x; ss0  = d * d;
        d = p0.y - g0.y; ss0 += d * d;
        d = p0.z - g0.z; ss0 += d * d;
        d = p0.w - g0.w; ss1  = d * d;
        d = p1.x - g1.x; ss1 += d * d;
        d = p1.y - g1.y; ss1 += d * d;
        d = p1.z - g1.z; ss2  = d * d;
        d = p1.w - g1.w; ss2 += d * d;
        d = p2.x - g2.x; ss2 += d * d;
        d = p2.y - g2.y; ss3  = d * d;
        d = p2.z - g2.z; ss3 += d * d;
        d = p2.w - g2.w; ss3 += d * d;
    }
    __syncthreads();   // sC4 + weights + s_mu ready

    // ---- ctrl MSE guard (uses published mu) ----
    float lc = 0.0f;
    {
        const int muB = s_mu;
        int i0 = (c0    ) >> 5, j0 = (c0    ) & 31;
        int i1 = (c0 + 1) >> 5, j1 = (c0 + 1) & 31;
        int i2 = (c0 + 2) >> 5, j2 = (c0 + 2) & 31;
        int i3 = (c0 + 3) >> 5, j3 = (c0 + 3) & 31;
        if (i0 < muB && j0 < mv) lc += ss0;
        if (i1 < muB && j1 < mv) lc += ss1;
        if (i2 < muB && j2 < mv) lc += ss2;
        if (i3 < muB && j3 < mv) lc += ss3;
    }

    // ---- fused stage 1+2, vectorized LDS.128 everywhere ----
    float ls = 0.0f;
    {
        const int v0 = 2 * lane, v1 = v0 + 1;
        const float4 w0 = wV4[v0],  w1 = wV4[v1];
        const int    jv0 = baseV[v0], jv1 = baseV[v1];
        float4* twb = sT4 + warp * 64;

#pragma unroll
        for (int k = 0; k < 8; k++) {
            const int u = warp * 8 + k;
            float4* tw = twb + (k & 1) * 32;

            // stage 1: lane j computes T[u][j] -> 4 LDS.128 + 1 STS.128
            {
                float4 wu = wU4[u];
                const float4* cr = &sC4[baseU[u] * NM + lane];
                float4 r0 = cr[0], r1 = cr[NM], r2 = cr[2 * NM], r3 = cr[3 * NM];
                tw[lane] = make_float4(
                    wu.x * r0.x + wu.y * r1.x + wu.z * r2.x + wu.w * r3.x,
                    wu.x * r0.y + wu.y * r1.y + wu.z * r2.y + wu.w * r3.y,
                    wu.x * r0.z + wu.y * r1.z + wu.z * r2.z + wu.w * r3.z, 0.0f);
            }
            __syncwarp();

            // rotate xyz prefetch (distance 1)
            float2 C0 = A0, C1 = A1, C2 = A2;
            if (k < 7) {
                const float* xn = xw + (k + 1) * 192;
                A0 = __ldcs((const float2*)(xn));
                A1 = __ldcs((const float2*)(xn + 2));
                A2 = __ldcs((const float2*)(xn + 4));
            }

            // stage 2: 8 LDS.128 gathers + dot products
            float4 q0 = tw[jv0], q1 = tw[jv0 + 1], q2 = tw[jv0 + 2], q3 = tw[jv0 + 3];
            float4 s0 = tw[jv1], s1 = tw[jv1 + 1], s2 = tw[jv1 + 2], s3 = tw[jv1 + 3];
            float n00 = w0.x * q0.x + w0.y * q1.x + w0.z * q2.x + w0.w * q3.x;
            float n01 = w0.x * q0.y + w0.y * q1.y + w0.z * q2.y + w0.w * q3.y;
            float n02 = w0.x * q0.z + w0.y * q1.z + w0.z * q2.z + w0.w * q3.z;
            float n10 = w1.x * s0.x + w1.y * s1.x + w1.z * s2.x + w1.w * s3.x;
            float n11 = w1.x * s0.y + w1.y * s1.y + w1.z * s2.y + w1.w * s3.y;
            float n12 = w1.x * s0.z + w1.y * s1.z + w1.z * s2.z + w1.w * s3.z;
            float e;
            e = n00 - C0.x; ls += e * e;   // point v0 = (C0.x, C0.y, C1.x)
            e = n01 - C0.y; ls += e * e;
            e = n02 - C1.x; ls += e * e;
            e = n10 - C1.y; ls += e * e;   // point v1 = (C1.y, C2.x, C2.y)
            e = n11 - C2.x; ls += e * e;
            e = n12 - C2.y; ls += e * e;
            // NaN/Inf in surf propagates into ls; guard evaluated at end
        }
    }

    // ---- block reduction -> per-block partial ----
#pragma unroll
    for (int o = 16; o > 0; o >>= 1) {
        ls += __shfl_down_sync(0xffffffffu, ls, o);
        lc += __shfl_down_sync(0xffffffffu, lc, o);
    }
    if (lane == 0) { rS[warp] = ls; rC[warp] = lc; }
    __syncthreads();
    if (tid == 0) {
        float S = 0.0f, C = 0.0f;
#pragma unroll
        for (int i = 0; i < 8; i++) { S += rS[i]; C += rC[i]; }
        g_part[b] = make_float4(S, C, (float)(mu * mv), 0.0f);
        __threadfence();
        unsigned t = atomicAdd(&g_count, 1u);
        s_last = (t == BATCH - 1) ? 1 : 0;
    }
    __syncthreads();

    // ---- last block: global reduction + output (fused finalize) ----
    if (s_last) {
        __threadfence();
        double s = 0.0, c = 0.0, m = 0.0;
#pragma unroll
        for (int i = tid; i < BATCH; i += 256) {
            float4 pt = g_part[i];
            s += (double)pt.x; c += (double)pt.y; m += (double)pt.z;
        }
#pragma unroll
        for (int o = 16; o > 0; o >>= 1) {
            s += __shfl_down_sync(0xffffffffu, s, o);
            c += __shfl_down_sync(0xffffffffu, c, o);
            m += __shfl_down_sync(0xffffffffu, m, o);
        }
        __shared__ double dS[8], dC[8], dM[8];
        if (lane == 0) { dS[warp] = s; dC[warp] = c; dM[warp] = m; }
        __syncthreads();
        if (tid == 0) {
            double S = 0.0, C = 0.0, M = 0.0;
#pragma unroll
            for (int i = 0; i < 8; i++) { S += dS[i]; C += dC[i]; M += dM[i]; }
            double denom = M * 3.0; if (denom < 1.0) denom = 1.0;
            double loss_ctrl = C / denom;
            double loss_surf = S / (double)((long long)BATCH * NU * NU * 3);
            float lcf = (float)loss_ctrl;
            float lsf = (float)loss_surf;
            out[0] = lcf + lsf;                 // total (pre nan-guard, W=1)
            out[1] = lcf;                       // loss_ctrl
            unsigned ub = __float_as_uint(lsf);
            bool bad = ((ub & 0x7f800000u) == 0x7f800000u);
            out[2] = bad ? 1e6f : lsf;          // surf_mse (guarded)
            g_count = 0;                        // reset for next graph replay
        }
    }
}

extern "C" void kernel_launch(void* const* d_in, const int* in_sizes, int n_in,
                              void* d_out, int out_size) {
    const float* ctrl_pred = (const float*)d_in[0];   // (B,32,32,3)
    const float* ctrl_gt   = (const float*)d_in[1];   // (B,32,32,3)
    const float* mask      = (const float*)d_in[2];   // (B,32,32)
    const float* xyz       = (const float*)d_in[3];   // (B,64,64,3)
    float* out = (float*)d_out;

    size_t smem_bytes = SMEM_FLOATS * sizeof(float);  // 27136 B
    cudaFuncSetAttribute(surf_loss_kernel,
                         cudaFuncAttributeMaxDynamicSharedMemorySize,
                         (int)smem_bytes);

    surf_loss_kernel<<<BATCH, 256, smem_bytes>>>(ctrl_pred, ctrl_gt, mask, xyz, out);
}

// round 17
// speedup vs baseline: 1.1686x; 1.1686x over previous
#include <cuda_runtime.h>
#include <cstdint>
#include <math.h>

#define DEG 3
#define NM 32          // MU_MAX = MV_MAX
#define NU 64          // OUT_U = OUT_V
#define BATCH 1024
#define EPSI 1e-5f

// per-block partials: x = surf-sq-err sum, y = ctrl-sq-err sum, z = mask sum
__device__ float4 g_part[BATCH];
__device__ unsigned g_count = 0;   // last-block counter; reset each launch

// clamped open-uniform knot, n_valid = m ctrl pts (matches reference padding)
__device__ __forceinline__ float kvf(int k, int m) {
    if (k <= DEG) return 0.0f;
    if (k >= m)   return 1.0f;
    return (float)k / (float)(m + DEG);
}

// ---------------- smem layout (floats) ----------------
//  sCf   float[3072]  : 0      ctrl_pred packed xyz (12 KB)
//  wU4   float4[64]   : 3072   (denominator-folded weights)
//  wV4   float4[64]   : 3328
//  baseU int[64]      : 3584
//  baseV int[64]      : 3648
//  total 3712 floats = 14848 B   (no sT — T lives in registers, gathered via SHFL)
#define SMEM_FLOATS 3712

__global__ __launch_bounds__(256, 4)
void surf_loss_kernel(const float* __restrict__ ctrl_pred,
                      const float* __restrict__ ctrl_gt,
                      const float* __restrict__ mask,
                      const float* __restrict__ xyz,
                      float* __restrict__ out) {
    extern __shared__ float sm[];
    float*  sCf   = sm;
    float4* wU4   = (float4*)(sm + 3072);
    float4* wV4   = (float4*)(sm + 3328);
    int*    baseU = (int*)(sm + 3584);
    int*    baseV = (int*)(sm + 3648);

    __shared__ float rS[8], rC[8];
    __shared__ int s_mu, s_last;

    const int b    = blockIdx.x;
    const int tid  = threadIdx.x;
    const int lane = tid & 31;
    const int warp = tid >> 5;
    const unsigned FULL = 0xffffffffu;

    // ================== PROLOGUE: issue long-latency loads first ==================
    const float* mk = mask + (size_t)b * (NM * NM);
    float mrow = mk[lane];                                   // row 0 -> mv (1 line)
    float mcol = (warp < 2) ? mk[lane * NM] : 0.0f;          // col 0 -> mu (warps 0-1)

    const float4* cp4 = (const float4*)(ctrl_pred + (size_t)b * (NM * NM * 3));
    const float4* cg4 = (const float4*)(ctrl_gt   + (size_t)b * (NM * NM * 3));
    const int kc = 3 * tid;
    float4 p0 = __ldcs(&cp4[kc]), p1 = __ldcs(&cp4[kc + 1]), p2 = __ldcs(&cp4[kc + 2]);
    float4 g0 = __ldcs(&cg4[kc]), g1 = __ldcs(&cg4[kc + 1]), g2 = __ldcs(&cg4[kc + 2]);

    const float* xw = xyz + (size_t)b * (NU * NU * 3) + (warp * 8) * 192 + 6 * lane;
    float2 A0 = __ldcs((const float2*)(xw));
    float2 A1 = __ldcs((const float2*)(xw + 2));
    float2 A2 = __ldcs((const float2*)(xw + 4));

    // ---- ragged sizes ----
    unsigned bmv = __ballot_sync(FULL, mrow > 0.0f);
    const int mv = max(__popc(bmv), DEG + 1);
    int mu = DEG + 1;
    if (warp < 2) {
        unsigned bmu = __ballot_sync(FULL, mcol > 0.0f);
        mu = max(__popc(bmu), DEG + 1);
    }
    if (tid == 0) s_mu = mu;

    // ---- local de Boor: warps 0-1 use mu, warps 2-3 use mv ----
    if (tid < 128) {
        int dim = tid >> 6, g = tid & 63;
        int m = dim ? mv : mu;
        float x = EPSI + ((1.0f - 2.0f * EPSI) / 63.0f) * (float)g;
        int s = (int)(x * (float)(m + DEG));
        s = max(s, DEG); s = min(s, m - 1);
        while (s < m - 1 && x >= kvf(s + 1, m)) s++;
        while (s > DEG && x < kvf(s, m)) s--;
        float N[4]; N[0] = 1.0f; N[1] = N[2] = N[3] = 0.0f;
        float left[4], right[4];
#pragma unroll
        for (int d = 1; d <= DEG; d++) {
            left[d]  = x - kvf(s + 1 - d, m);
            right[d] = kvf(s + d, m) - x;
            float saved = 0.0f;
#pragma unroll
            for (int r = 0; r < d; r++) {
                float tmp = N[r] / (right[r + 1] + left[d - r]);
                N[r] = saved + right[r + 1] * tmp;
                saved = left[d - r] * tmp;
            }
            N[d] = saved;
        }
        float inv = 1.0f / (N[0] + N[1] + N[2] + N[3]);  // partition denom
        float4 w = make_float4(N[0] * inv, N[1] * inv, N[2] * inv, N[3] * inv);
        if (dim == 0) { wU4[g] = w; baseU[g] = s - DEG; }
        else          { wV4[g] = w; baseV[g] = s - DEG; }
    }

    // ---- stage ctrl into packed smem + squared diffs (guard after barrier) ----
    const int c0 = 4 * tid;
    float ss0, ss1, ss2, ss3;
    {
        float4* sC4w = (float4*)sCf;
        sC4w[kc] = p0; sC4w[kc + 1] = p1; sC4w[kc + 2] = p2;
        float d;
        d = p0.x - g0.x; ss0  = d * d;
        d = p0.y - g0.y; ss0 += d * d;
        d = p0.z - g0.z; ss0 += d * d;
        d = p0.w - g0.w; ss1  = d * d;
        d = p1.x - g1.x; ss1 += d * d;
        d = p1.y - g1.y; ss1 += d * d;
        d = p1.z - g1.z; ss2  = d * d;
        d = p1.w - g1.w; ss2 += d * d;
        d = p2.x - g2.x; ss2 += d * d;
        d = p2.y - g2.y; ss3  = d * d;
        d = p2.z - g2.z; ss3 += d * d;
        d = p2.w - g2.w; ss3 += d * d;
    }
    __syncthreads();   // the ONLY block barrier: sCf + weights + s_mu ready

    // ---- ctrl MSE guard (uses published mu) ----
    float lc = 0.0f;
    {
        const int muB = s_mu;
        int i0 = (c0    ) >> 5, j0 = (c0    ) & 31;
        int i1 = (c0 + 1) >> 5, j1 = (c0 + 1) & 31;
        int i2 = (c0 + 2) >> 5, j2 = (c0 + 2) & 31;
        int i3 = (c0 + 3) >> 5, j3 = (c0 + 3) & 31;
        if (i0 < muB && j0 < mv) lc += ss0;
        if (i1 < muB && j1 < mv) lc += ss1;
        if (i2 < muB && j2 < mv) lc += ss2;
        if (i3 < muB && j3 < mv) lc += ss3;
    }

    // ---- fused stage 1+2: T in registers, SHFL gather (no STS, no syncwarp) ----
    float ls = 0.0f;
    {
        const int v0 = 2 * lane, v1 = v0 + 1;
        const float4 w0 = wV4[v0], w1 = wV4[v1];
        const int    jv0 = baseV[v0], jv1 = baseV[v1];

#pragma unroll
        for (int k = 0; k < 8; k++) {
            const int u = warp * 8 + k;

            // stage 1: lane j computes T[u][j] into registers (12 LDS, conflict-free)
            float4 wu = wU4[u];
            const float* cc = &sCf[(baseU[u] * NM + lane) * 3];
            float tx = wu.x * cc[0] + wu.y * cc[96] + wu.z * cc[192] + wu.w * cc[288];
            float ty = wu.x * cc[1] + wu.y * cc[97] + wu.z * cc[193] + wu.w * cc[289];
            float tz = wu.x * cc[2] + wu.y * cc[98] + wu.z * cc[194] + wu.w * cc[290];

            // rotate xyz prefetch (distance 1)
            float2 C0 = A0, C1 = A1, C2 = A2;
            if (k < 7) {
                const float* xn = xw + (k + 1) * 192;
                A0 = __ldcs((const float2*)(xn));
                A1 = __ldcs((const float2*)(xn + 2));
                A2 = __ldcs((const float2*)(xn + 4));
            }

            // stage 2: gather 4 sparse taps per v via dynamic-index shuffles
            float q0x = __shfl_sync(FULL, tx, jv0),     q0y = __shfl_sync(FULL, ty, jv0),     q0z = __shfl_sync(FULL, tz, jv0);
            float q1x = __shfl_sync(FULL, tx, jv0 + 1), q1y = __shfl_sync(FULL, ty, jv0 + 1), q1z = __shfl_sync(FULL, tz, jv0 + 1);
            float q2x = __shfl_sync(FULL, tx, jv0 + 2), q2y = __shfl_sync(FULL, ty, jv0 + 2), q2z = __shfl_sync(FULL, tz, jv0 + 2);
            float q3x = __shfl_sync(FULL, tx, jv0 + 3), q3y = __shfl_sync(FULL, ty, jv0 + 3), q3z = __shfl_sync(FULL, tz, jv0 + 3);
            float s0x = __shfl_sync(FULL, tx, jv1),     s0y = __shfl_sync(FULL, ty, jv1),     s0z = __shfl_sync(FULL, tz, jv1);
            float s1x = __shfl_sync(FULL, tx, jv1 + 1), s1y = __shfl_sync(FULL, ty, jv1 + 1), s1z = __shfl_sync(FULL, tz, jv1 + 1);
            float s2x = __shfl_sync(FULL, tx, jv1 + 2), s2y = __shfl_sync(FULL, ty, jv1 + 2), s2z = __shfl_sync(FULL, tz, jv1 + 2);
            float s3x = __shfl_sync(FULL, tx, jv1 + 3), s3y = __shfl_sync(FULL, ty, jv1 + 3), s3z = __shfl_sync(FULL, tz, jv1 + 3);

            float n00 = w0.x * q0x + w0.y * q1x + w0.z * q2x + w0.w * q3x;
            float n01 = w0.x * q0y + w0.y * q1y + w0.z * q2y + w0.w * q3y;
            float n02 = w0.x * q0z + w0.y * q1z + w0.z * q2z + w0.w * q3z;
            float n10 = w1.x * s0x + w1.y * s1x + w1.z * s2x + w1.w * s3x;
            float n11 = w1.x * s0y + w1.y * s1y + w1.z * s2y + w1.w * s3y;
            float n12 = w1.x * s0z + w1.y * s1z + w1.z * s2z + w1.w * s3z;

            float e;
            e = n00 - C0.x; ls += e * e;   // point v0 = (C0.x, C0.y, C1.x)
            e = n01 - C0.y; ls += e * e;
            e = n02 - C1.x; ls += e * e;
            e = n10 - C1.y; ls += e * e;   // point v1 = (C1.y, C2.x, C2.y)
            e = n11 - C2.x; ls += e * e;
            e = n12 - C2.y; ls += e * e;
            // NaN/Inf in surf propagates into ls; guard evaluated at end
        }
    }

    // ---- block reduction -> per-block partial ----
#pragma unroll
    for (int o = 16; o > 0; o >>= 1) {
        ls += __shfl_down_sync(FULL, ls, o);
        lc += __shfl_down_sync(FULL, lc, o);
    }
    if (lane == 0) { rS[warp] = ls; rC[warp] = lc; }
    __syncthreads();
    if (tid == 0) {
        float S = 0.0f, C = 0.0f;
#pragma unroll
        for (int i = 0; i < 8; i++) { S += rS[i]; C += rC[i]; }
        g_part[b] = make_float4(S, C, (float)(s_mu * mv), 0.0f);
        __threadfence();
        unsigned t = atomicAdd(&g_count, 1u);
        s_last = (t == BATCH - 1) ? 1 : 0;
    }
    __syncthreads();

    // ---- last block: global reduction + output (fused finalize) ----
    if (s_last) {
        __threadfence();
        double s = 0.0, c = 0.0, m = 0.0;
#pragma unroll
        for (int i = tid; i < BATCH; i += 256) {
            float4 pt = g_part[i];
            s += (double)pt.x; c += (double)pt.y; m += (double)pt.z;
        }
#pragma unroll
        for (int o = 16; o > 0; o >>= 1) {
            s += __shfl_down_sync(FULL, s, o);
            c += __shfl_down_sync(FULL, c, o);
            m += __shfl_down_sync(FULL, m, o);
        }
        __shared__ double dS[8], dC[8], dM[8];
        if (lane == 0) { dS[warp] = s; dC[warp] = c; dM[warp] = m; }
        __syncthreads();
        if (tid == 0) {
            double S = 0.0, C = 0.0, M = 0.0;
#pragma unroll
            for (int i = 0; i < 8; i++) { S += dS[i]; C += dC[i]; M += dM[i]; }
            double denom = M * 3.0; if (denom < 1.0) denom = 1.0;
            double loss_ctrl = C / denom;
            double loss_surf = S / (double)((long long)BATCH * NU * NU * 3);
            float lcf = (float)loss_ctrl;
            float lsf = (float)loss_surf;
            out[0] = lcf + lsf;                 // total (pre nan-guard, W=1)
            out[1] = lcf;                       // loss_ctrl
            unsigned ub = __float_as_uint(lsf);
            bool bad = ((ub & 0x7f800000u) == 0x7f800000u);
            out[2] = bad ? 1e6f : lsf;          // surf_mse (guarded)
            g_count = 0;                        // reset for next graph replay
        }
    }
}

extern "C" void kernel_launch(void* const* d_in, const int* in_sizes, int n_in,
                              void* d_out, int out_size) {
    const float* ctrl_pred = (const float*)d_in[0];   // (B,32,32,3)
    const float* ctrl_gt   = (const float*)d_in[1];   // (B,32,32,3)
    const float* mask      = (const float*)d_in[2];   // (B,32,32)
    const float* xyz       = (const float*)d_in[3];   // (B,64,64,3)
    float* out = (float*)d_out;

    size_t smem_bytes = SMEM_FLOATS * sizeof(float);  // 14848 B
    cudaFuncSetAttribute(surf_loss_kernel,
                         cudaFuncAttributeMaxDynamicSharedMemorySize,
                         (int)smem_bytes);

    surf_loss_kernel<<<BATCH, 256, smem_bytes>>>(ctrl_pred, ctrl_gt, mask, xyz, out);
}